// round 1
// baseline (speedup 1.0000x reference)
#include <cuda_runtime.h>
#include <math.h>

#define N_PTS 32768
#define DIM   512
#define NC    64
#define KM_ITERS 10

#define ACC_BLOCKS 128
#define CHUNK (N_PTS / ACC_BLOCKS)   // 256

#define KC 32
#define XS_STRIDE 132   // 128 + 4 pad, multiple of 4 (float4-aligned rows)
#define WS_STRIDE 72    // 64 + 8 pad, multiple of 4

// ---- scratch (no allocations allowed) ----
__device__ float g_centers[NC * DIM];
__device__ float g_b2[NC];
__device__ int   g_assign[N_PTS];
__device__ float g_psum[(size_t)ACC_BLOCKS * NC * DIM];   // 16 MB partials
__device__ float g_pcnt[ACC_BLOCKS * NC];

// ============================================================================
// init: centers = data[:64], b2 = ||c||^2
// grid 64, block 128
// ============================================================================
__global__ void init_kernel(const float* __restrict__ X) {
    int c = blockIdx.x;
    int t = threadIdx.x;           // 0..127, handles 4 dims via float4
    const float4* xr = (const float4*)(X + (size_t)c * DIM);
    float4 v = xr[t];
    ((float4*)(g_centers + (size_t)c * DIM))[t] = v;
    float s = v.x * v.x + v.y * v.y + v.z * v.z + v.w * v.w;
    __shared__ float red[128];
    red[t] = s;
    __syncthreads();
    for (int o = 64; o > 0; o >>= 1) {
        if (t < o) red[t] += red[t + o];
        __syncthreads();
    }
    if (t == 0) g_b2[c] = red[0];
}

// ============================================================================
// assign: argmin_c ( b2[c] - 2 * x . c )   (dropping constant ||x||^2)
// block tile: 128 points x 64 clusters, 256 threads, thread tile 4x8
// grid = N_PTS/128 = 256
// ============================================================================
__global__ __launch_bounds__(256) void assign_kernel(const float* __restrict__ X) {
    __shared__ __align__(16) float Xs[KC * XS_STRIDE];
    __shared__ __align__(16) float Ws[KC * WS_STRIDE];
    __shared__ float sb2[NC];
    __shared__ float sval[128 * 8];
    __shared__ int   sidx[128 * 8];

    int tid = threadIdx.x;
    int tx = tid & 31;        // point group: points 4*tx .. 4*tx+3
    int ty = tid >> 5;        // cluster group: clusters 8*ty .. 8*ty+7
    int P0 = blockIdx.x * 128;

    if (tid < NC) sb2[tid] = g_b2[tid];

    float acc[4][8];
#pragma unroll
    for (int i = 0; i < 4; i++)
#pragma unroll
        for (int j = 0; j < 8; j++) acc[i][j] = 0.0f;

    const float4* X4 = (const float4*)X;
    const float4* W4 = (const float4*)g_centers;

    for (int kc4 = 0; kc4 < DIM / 4; kc4 += KC / 4) {
        // load 128x32 X tile, transposed into Xs[k][p]
#pragma unroll
        for (int r = 0; r < 4; r++) {
            int q = tid + r * 256;           // 0..1023
            int p = q >> 3;                  // 0..127
            int j = q & 7;                   // float4 within the 32-k chunk
            float4 v = X4[(size_t)(P0 + p) * (DIM / 4) + kc4 + j];
            int kk = j * 4;
            Xs[(kk + 0) * XS_STRIDE + p] = v.x;
            Xs[(kk + 1) * XS_STRIDE + p] = v.y;
            Xs[(kk + 2) * XS_STRIDE + p] = v.z;
            Xs[(kk + 3) * XS_STRIDE + p] = v.w;
        }
        // load 64x32 W tile, transposed into Ws[k][c]
#pragma unroll
        for (int r = 0; r < 2; r++) {
            int q = tid + r * 256;           // 0..511
            int c = q >> 3;                  // 0..63
            int j = q & 7;
            float4 v = W4[(size_t)c * (DIM / 4) + kc4 + j];
            int kk = j * 4;
            Ws[(kk + 0) * WS_STRIDE + c] = v.x;
            Ws[(kk + 1) * WS_STRIDE + c] = v.y;
            Ws[(kk + 2) * WS_STRIDE + c] = v.z;
            Ws[(kk + 3) * WS_STRIDE + c] = v.w;
        }
        __syncthreads();
#pragma unroll 8
        for (int k = 0; k < KC; k++) {
            float xr[4], wr[8];
            *(float4*)&xr[0] = *(const float4*)&Xs[k * XS_STRIDE + tx * 4];
            *(float4*)&wr[0] = *(const float4*)&Ws[k * WS_STRIDE + ty * 8];
            *(float4*)&wr[4] = *(const float4*)&Ws[k * WS_STRIDE + ty * 8 + 4];
#pragma unroll
            for (int i = 0; i < 4; i++)
#pragma unroll
                for (int j = 0; j < 8; j++)
                    acc[i][j] += xr[i] * wr[j];
        }
        __syncthreads();
    }

    // per-thread argmin over its 8 clusters (ascending index, strict <)
#pragma unroll
    for (int i = 0; i < 4; i++) {
        float mv = 3.4e38f;
        int mi = 0;
#pragma unroll
        for (int j = 0; j < 8; j++) {
            float s = sb2[ty * 8 + j] - 2.0f * acc[i][j];
            if (s < mv) { mv = s; mi = ty * 8 + j; }
        }
        int p = tx * 4 + i;
        sval[p * 8 + ty] = mv;
        sidx[p * 8 + ty] = mi;
    }
    __syncthreads();
    // reduce 8 candidates per point (ascending ty == ascending cluster ranges)
    if (tid < 128) {
        float mv = sval[tid * 8];
        int mi = sidx[tid * 8];
#pragma unroll
        for (int t = 1; t < 8; t++) {
            float v = sval[tid * 8 + t];
            if (v < mv) { mv = v; mi = sidx[tid * 8 + t]; }
        }
        g_assign[P0 + tid] = mi;
    }
}

// ============================================================================
// accumulate: per-block shared accumulator (64x512 fp32 = 128 KB), warp-private
// dim slices (no atomics in hot loop). grid ACC_BLOCKS, block 256.
// ============================================================================
__global__ __launch_bounds__(256) void accum_kernel(const float* __restrict__ X) {
    extern __shared__ float sm[];
    float* sacc = sm;                       // NC*DIM
    float* scnt = sm + NC * DIM;            // NC
    int*   sassign = (int*)(scnt + NC);     // CHUNK

    int tid = threadIdx.x;
    for (int i = tid; i < NC * DIM; i += 256) sacc[i] = 0.0f;
    for (int i = tid; i < NC; i += 256) scnt[i] = 0.0f;
    int base = blockIdx.x * CHUNK;
    for (int i = tid; i < CHUNK; i += 256) sassign[i] = g_assign[base + i];
    __syncthreads();

    int w = tid >> 5, lane = tid & 31;
    int doff = w * 32 + lane;               // float2 offset: warp w owns dims [64w,64w+64)
    const float2* X2 = (const float2*)X;
    float2* sacc2 = (float2*)sacc;

    for (int p = 0; p < CHUNK; p++) {
        int a = sassign[p];
        float2 v = X2[(size_t)(base + p) * (DIM / 2) + doff];
        float2* ap = &sacc2[a * (DIM / 2) + doff];
        float2 cur = *ap;
        cur.x += v.x; cur.y += v.y;
        *ap = cur;
    }
    __syncthreads();
    for (int i = tid; i < CHUNK; i += 256) atomicAdd(&scnt[sassign[i]], 1.0f);
    __syncthreads();

    float* ps = g_psum + (size_t)blockIdx.x * NC * DIM;
    for (int i = tid; i < NC * DIM; i += 256) ps[i] = sacc[i];
    if (tid < NC) g_pcnt[blockIdx.x * NC + tid] = scnt[tid];
}

// ============================================================================
// update: reduce partials -> new centers (keep old if empty), fused ||c||^2
// grid 64 (one per cluster), block 128 (4 dims each via float4)
// ============================================================================
__global__ void update_kernel() {
    int c = blockIdx.x;
    int t = threadIdx.x;
    __shared__ float s_cnt;
    __shared__ float red[128];

    if (t < 32) {
        float cs = 0.0f;
        for (int b = t; b < ACC_BLOCKS; b += 32) cs += g_pcnt[b * NC + c];
        for (int o = 16; o > 0; o >>= 1) cs += __shfl_down_sync(0xffffffffu, cs, o);
        if (t == 0) s_cnt = cs;
    }
    __syncthreads();
    float cnt = s_cnt;

    const float4* ps4 = (const float4*)g_psum;
    float4 s = make_float4(0.f, 0.f, 0.f, 0.f);
    for (int b = 0; b < ACC_BLOCKS; b++) {
        float4 v = ps4[(size_t)b * (NC * DIM / 4) + c * (DIM / 4) + t];
        s.x += v.x; s.y += v.y; s.z += v.z; s.w += v.w;
    }
    float4* cen4 = (float4*)g_centers;
    float4 oldc = cen4[(size_t)c * (DIM / 4) + t];
    float4 nc;
    if (cnt > 0.0f) {
        float inv = 1.0f / cnt;
        nc.x = s.x * inv; nc.y = s.y * inv; nc.z = s.z * inv; nc.w = s.w * inv;
    } else {
        nc = oldc;
    }
    cen4[(size_t)c * (DIM / 4) + t] = nc;

    float sq = nc.x * nc.x + nc.y * nc.y + nc.z * nc.z + nc.w * nc.w;
    red[t] = sq;
    __syncthreads();
    for (int o = 64; o > 0; o >>= 1) {
        if (t < o) red[t] += red[t + o];
        __syncthreads();
    }
    if (t == 0) g_b2[c] = red[0];
}

// ============================================================================
// final: out[p][c] = 1 / (sqrt(max(||x||^2 + ||c||^2 - 2 x.c, 0)) + 1e-8)
// same GEMM structure; ||x||^2 fused into warp ty==0 of the mainloop
// ============================================================================
__global__ __launch_bounds__(256) void final_kernel(const float* __restrict__ X,
                                                    float* __restrict__ out) {
    __shared__ __align__(16) float Xs[KC * XS_STRIDE];
    __shared__ __align__(16) float Ws[KC * WS_STRIDE];
    __shared__ float sb2[NC];
    __shared__ float sa2[128];

    int tid = threadIdx.x;
    int tx = tid & 31, ty = tid >> 5;
    int P0 = blockIdx.x * 128;

    if (tid < NC) sb2[tid] = g_b2[tid];

    float acc[4][8];
#pragma unroll
    for (int i = 0; i < 4; i++)
#pragma unroll
        for (int j = 0; j < 8; j++) acc[i][j] = 0.0f;
    float a2acc[4] = {0.f, 0.f, 0.f, 0.f};

    const float4* X4 = (const float4*)X;
    const float4* W4 = (const float4*)g_centers;

    for (int kc4 = 0; kc4 < DIM / 4; kc4 += KC / 4) {
#pragma unroll
        for (int r = 0; r < 4; r++) {
            int q = tid + r * 256;
            int p = q >> 3;
            int j = q & 7;
            float4 v = X4[(size_t)(P0 + p) * (DIM / 4) + kc4 + j];
            int kk = j * 4;
            Xs[(kk + 0) * XS_STRIDE + p] = v.x;
            Xs[(kk + 1) * XS_STRIDE + p] = v.y;
            Xs[(kk + 2) * XS_STRIDE + p] = v.z;
            Xs[(kk + 3) * XS_STRIDE + p] = v.w;
        }
#pragma unroll
        for (int r = 0; r < 2; r++) {
            int q = tid + r * 256;
            int c = q >> 3;
            int j = q & 7;
            float4 v = W4[(size_t)c * (DIM / 4) + kc4 + j];
            int kk = j * 4;
            Ws[(kk + 0) * WS_STRIDE + c] = v.x;
            Ws[(kk + 1) * WS_STRIDE + c] = v.y;
            Ws[(kk + 2) * WS_STRIDE + c] = v.z;
            Ws[(kk + 3) * WS_STRIDE + c] = v.w;
        }
        __syncthreads();
#pragma unroll 8
        for (int k = 0; k < KC; k++) {
            float xr[4], wr[8];
            *(float4*)&xr[0] = *(const float4*)&Xs[k * XS_STRIDE + tx * 4];
            *(float4*)&wr[0] = *(const float4*)&Ws[k * WS_STRIDE + ty * 8];
            *(float4*)&wr[4] = *(const float4*)&Ws[k * WS_STRIDE + ty * 8 + 4];
            if (ty == 0) {
#pragma unroll
                for (int i = 0; i < 4; i++) a2acc[i] += xr[i] * xr[i];
            }
#pragma unroll
            for (int i = 0; i < 4; i++)
#pragma unroll
                for (int j = 0; j < 8; j++)
                    acc[i][j] += xr[i] * wr[j];
        }
        __syncthreads();
    }

    if (ty == 0) {
#pragma unroll
        for (int i = 0; i < 4; i++) sa2[tx * 4 + i] = a2acc[i];
    }
    __syncthreads();

#pragma unroll
    for (int i = 0; i < 4; i++) {
        float a2 = sa2[tx * 4 + i];
        float res[8];
#pragma unroll
        for (int j = 0; j < 8; j++) {
            float d2 = a2 + sb2[ty * 8 + j] - 2.0f * acc[i][j];
            d2 = fmaxf(d2, 0.0f);
            res[j] = 1.0f / (sqrtf(d2) + 1e-8f);
        }
        float* op = out + (size_t)(P0 + tx * 4 + i) * NC + ty * 8;
        *(float4*)&op[0] = *(float4*)&res[0];
        *(float4*)&op[4] = *(float4*)&res[4];
    }
}

// ============================================================================
extern "C" void kernel_launch(void* const* d_in, const int* in_sizes, int n_in,
                              void* d_out, int out_size) {
    const float* X = (const float*)d_in[0];
    float* out = (float*)d_out;

    const int smem_acc = (NC * DIM + NC + CHUNK) * 4;   // ~132.3 KB
    cudaFuncSetAttribute(accum_kernel,
                         cudaFuncAttributeMaxDynamicSharedMemorySize, smem_acc);

    init_kernel<<<NC, 128>>>(X);
    for (int it = 0; it < KM_ITERS; it++) {
        assign_kernel<<<N_PTS / 128, 256>>>(X);
        accum_kernel<<<ACC_BLOCKS, 256, smem_acc>>>(X);
        update_kernel<<<NC, 128>>>();
    }
    final_kernel<<<N_PTS / 128, 256>>>(X, out);
}

// round 12
// speedup vs baseline: 1.0381x; 1.0381x over previous
#include <cuda_runtime.h>
#include <math.h>
#include <stdint.h>

#define N_PTS 32768
#define DIM   512
#define NC    64
#define KM_ITERS 10

#define ACC_BLOCKS 128
#define CHUNK (N_PTS / ACC_BLOCKS)   // 256

#define KC 32
#define XS_STRIDE 132   // 128 + 4 pad, multiple of 4 (float4-aligned rows)
#define WS_STRIDE 72    // 64 + 8 pad, multiple of 4

typedef unsigned long long u64;

// ---- scratch (no allocations allowed) ----
__device__ float g_centers[NC * DIM];
__device__ float g_b2[NC];
__device__ int   g_assign[N_PTS];
__device__ float g_psum[(size_t)ACC_BLOCKS * NC * DIM];   // 16 MB partials
__device__ float g_pcnt[ACC_BLOCKS * NC];

// ---- packed f32x2 helpers (sm_100-family base feature) ----
__device__ __forceinline__ u64 pack2(float x) {
    u64 d;
    asm("mov.b64 %0, {%1, %1};" : "=l"(d) : "r"(__float_as_uint(x)));
    return d;
}
__device__ __forceinline__ void fma2(u64& acc, u64 a, u64 b) {
    asm("fma.rn.f32x2 %0, %1, %2, %0;" : "+l"(acc) : "l"(a), "l"(b));
}
__device__ __forceinline__ void unpack2(u64 v, float& lo, float& hi) {
    uint32_t a, b;
    asm("mov.b64 {%0, %1}, %2;" : "=r"(a), "=r"(b) : "l"(v));
    lo = __uint_as_float(a);
    hi = __uint_as_float(b);
}

// ============================================================================
// init: centers = data[:64], b2 = ||c||^2.   grid 64, block 128
// ============================================================================
__global__ void init_kernel(const float* __restrict__ X) {
    int c = blockIdx.x;
    int t = threadIdx.x;           // 0..127, handles 4 dims via float4
    const float4* xr = (const float4*)(X + (size_t)c * DIM);
    float4 v = xr[t];
    ((float4*)(g_centers + (size_t)c * DIM))[t] = v;
    float s = v.x * v.x + v.y * v.y + v.z * v.z + v.w * v.w;
    __shared__ float red[128];
    red[t] = s;
    __syncthreads();
    for (int o = 64; o > 0; o >>= 1) {
        if (t < o) red[t] += red[t + o];
        __syncthreads();
    }
    if (t == 0) g_b2[c] = red[0];
}

// ============================================================================
// assign: argmin_c ( b2[c] - 2 * x . c )   (dropping constant ||x||^2)
// block tile: 128 points x 64 clusters, 256 threads, thread tile 4x8
// f32x2 packed FMA mainloop.  grid = N_PTS/128 = 256
// ============================================================================
__global__ __launch_bounds__(256) void assign_kernel(const float* __restrict__ X) {
    __shared__ __align__(16) float Xs[KC * XS_STRIDE];
    __shared__ __align__(16) float Ws[KC * WS_STRIDE];
    __shared__ float sb2[NC];
    __shared__ float sval[128 * 8];
    __shared__ int   sidx[128 * 8];

    int tid = threadIdx.x;
    int tx = tid & 31;        // point group: points 4*tx .. 4*tx+3
    int ty = tid >> 5;        // cluster group: clusters 8*ty .. 8*ty+7
    int P0 = blockIdx.x * 128;

    if (tid < NC) sb2[tid] = g_b2[tid];

    u64 acc2[4][4];           // [point i][cluster pair p] -> cols (2p, 2p+1)
#pragma unroll
    for (int i = 0; i < 4; i++)
#pragma unroll
        for (int p = 0; p < 4; p++) acc2[i][p] = 0ull;

    const float4* X4 = (const float4*)X;
    const float4* W4 = (const float4*)g_centers;

    for (int kc4 = 0; kc4 < DIM / 4; kc4 += KC / 4) {
        // load 128x32 X tile, transposed into Xs[k][p]
#pragma unroll
        for (int r = 0; r < 4; r++) {
            int q = tid + r * 256;           // 0..1023
            int p = q >> 3;                  // 0..127
            int j = q & 7;                   // float4 within the 32-k chunk
            float4 v = X4[(size_t)(P0 + p) * (DIM / 4) + kc4 + j];
            int kk = j * 4;
            Xs[(kk + 0) * XS_STRIDE + p] = v.x;
            Xs[(kk + 1) * XS_STRIDE + p] = v.y;
            Xs[(kk + 2) * XS_STRIDE + p] = v.z;
            Xs[(kk + 3) * XS_STRIDE + p] = v.w;
        }
        // load 64x32 W tile, transposed into Ws[k][c]
#pragma unroll
        for (int r = 0; r < 2; r++) {
            int q = tid + r * 256;           // 0..511
            int c = q >> 3;                  // 0..63
            int j = q & 7;
            float4 v = W4[(size_t)c * (DIM / 4) + kc4 + j];
            int kk = j * 4;
            Ws[(kk + 0) * WS_STRIDE + c] = v.x;
            Ws[(kk + 1) * WS_STRIDE + c] = v.y;
            Ws[(kk + 2) * WS_STRIDE + c] = v.z;
            Ws[(kk + 3) * WS_STRIDE + c] = v.w;
        }
        __syncthreads();
#pragma unroll 8
        for (int k = 0; k < KC; k++) {
            float4 xv = *(const float4*)&Xs[k * XS_STRIDE + tx * 4];
            ulonglong2 wA = *(const ulonglong2*)&Ws[k * WS_STRIDE + ty * 8];
            ulonglong2 wB = *(const ulonglong2*)&Ws[k * WS_STRIDE + ty * 8 + 4];
            u64 xd0 = pack2(xv.x), xd1 = pack2(xv.y);
            u64 xd2 = pack2(xv.z), xd3 = pack2(xv.w);
            fma2(acc2[0][0], xd0, wA.x); fma2(acc2[0][1], xd0, wA.y);
            fma2(acc2[0][2], xd0, wB.x); fma2(acc2[0][3], xd0, wB.y);
            fma2(acc2[1][0], xd1, wA.x); fma2(acc2[1][1], xd1, wA.y);
            fma2(acc2[1][2], xd1, wB.x); fma2(acc2[1][3], xd1, wB.y);
            fma2(acc2[2][0], xd2, wA.x); fma2(acc2[2][1], xd2, wA.y);
            fma2(acc2[2][2], xd2, wB.x); fma2(acc2[2][3], xd2, wB.y);
            fma2(acc2[3][0], xd3, wA.x); fma2(acc2[3][1], xd3, wA.y);
            fma2(acc2[3][2], xd3, wB.x); fma2(acc2[3][3], xd3, wB.y);
        }
        __syncthreads();
    }

    // per-thread argmin over its 8 clusters (ascending index, strict <)
#pragma unroll
    for (int i = 0; i < 4; i++) {
        float mv = 3.4e38f;
        int mi = 0;
#pragma unroll
        for (int p = 0; p < 4; p++) {
            float lo, hi;
            unpack2(acc2[i][p], lo, hi);
            float s0 = sb2[ty * 8 + 2 * p] - 2.0f * lo;
            float s1 = sb2[ty * 8 + 2 * p + 1] - 2.0f * hi;
            if (s0 < mv) { mv = s0; mi = ty * 8 + 2 * p; }
            if (s1 < mv) { mv = s1; mi = ty * 8 + 2 * p + 1; }
        }
        int p = tx * 4 + i;
        sval[p * 8 + ty] = mv;
        sidx[p * 8 + ty] = mi;
    }
    __syncthreads();
    // reduce 8 candidates per point (ascending ty == ascending cluster ranges)
    if (tid < 128) {
        float mv = sval[tid * 8];
        int mi = sidx[tid * 8];
#pragma unroll
        for (int t = 1; t < 8; t++) {
            float v = sval[tid * 8 + t];
            if (v < mv) { mv = v; mi = sidx[tid * 8 + t]; }
        }
        g_assign[P0 + tid] = mi;
    }
}

// ============================================================================
// accumulate: per-block shared accumulator (64x512 fp32 = 128 KB), warp-private
// dim slices (no atomics in hot loop). grid ACC_BLOCKS, block 256.
// ============================================================================
__global__ __launch_bounds__(256) void accum_kernel(const float* __restrict__ X) {
    extern __shared__ float sm[];
    float* sacc = sm;                       // NC*DIM
    float* scnt = sm + NC * DIM;            // NC
    int*   sassign = (int*)(scnt + NC);     // CHUNK

    int tid = threadIdx.x;
    for (int i = tid; i < NC * DIM; i += 256) sacc[i] = 0.0f;
    for (int i = tid; i < NC; i += 256) scnt[i] = 0.0f;
    int base = blockIdx.x * CHUNK;
    for (int i = tid; i < CHUNK; i += 256) sassign[i] = g_assign[base + i];
    __syncthreads();

    int w = tid >> 5, lane = tid & 31;
    int doff = w * 32 + lane;               // float2 offset: warp w owns dims [64w,64w+64)
    const float2* X2 = (const float2*)X;
    float2* sacc2 = (float2*)sacc;

    for (int p = 0; p < CHUNK; p++) {
        int a = sassign[p];
        float2 v = X2[(size_t)(base + p) * (DIM / 2) + doff];
        float2* ap = &sacc2[a * (DIM / 2) + doff];
        float2 cur = *ap;
        cur.x += v.x; cur.y += v.y;
        *ap = cur;
    }
    __syncthreads();
    for (int i = tid; i < CHUNK; i += 256) atomicAdd(&scnt[sassign[i]], 1.0f);
    __syncthreads();

    float* ps = g_psum + (size_t)blockIdx.x * NC * DIM;
    for (int i = tid; i < NC * DIM; i += 256) ps[i] = sacc[i];
    if (tid < NC) g_pcnt[blockIdx.x * NC + tid] = scnt[tid];
}

// ============================================================================
// update: reduce partials -> new centers (keep old if empty), fused ||c||^2
// grid 64 (one per cluster), block 512 (one dim per thread, coalesced, MLP=4)
// ============================================================================
__global__ __launch_bounds__(512) void update_kernel() {
    int c = blockIdx.x;
    int t = threadIdx.x;
    __shared__ float red[512];

    float cs = (t < ACC_BLOCKS) ? g_pcnt[t * NC + c] : 0.0f;
    red[t] = cs;
    __syncthreads();
    for (int o = 256; o > 0; o >>= 1) {
        if (t < o) red[t] += red[t + o];
        __syncthreads();
    }
    float cnt = red[0];
    __syncthreads();

    const float* ps = g_psum + (size_t)c * DIM + t;
    float s0 = 0.f, s1 = 0.f, s2 = 0.f, s3 = 0.f;
#pragma unroll 8
    for (int b = 0; b < ACC_BLOCKS; b += 4) {
        s0 += ps[(size_t)(b + 0) * (NC * DIM)];
        s1 += ps[(size_t)(b + 1) * (NC * DIM)];
        s2 += ps[(size_t)(b + 2) * (NC * DIM)];
        s3 += ps[(size_t)(b + 3) * (NC * DIM)];
    }
    float s = (s0 + s1) + (s2 + s3);

    float oldc = g_centers[c * DIM + t];
    float nc = (cnt > 0.0f) ? s / cnt : oldc;
    g_centers[c * DIM + t] = nc;

    red[t] = nc * nc;
    __syncthreads();
    for (int o = 256; o > 0; o >>= 1) {
        if (t < o) red[t] += red[t + o];
        __syncthreads();
    }
    if (t == 0) g_b2[c] = red[0];
}

// ============================================================================
// final: out[p][c] = 1 / (sqrt(max(||x||^2 + ||c||^2 - 2 x.c, 0)) + 1e-8)
// same GEMM structure; ||x||^2 fused into warp ty==0 of the mainloop
// ============================================================================
__global__ __launch_bounds__(256) void final_kernel(const float* __restrict__ X,
                                                    float* __restrict__ out) {
    __shared__ __align__(16) float Xs[KC * XS_STRIDE];
    __shared__ __align__(16) float Ws[KC * WS_STRIDE];
    __shared__ float sb2[NC];
    __shared__ float sa2[128];

    int tid = threadIdx.x;
    int tx = tid & 31, ty = tid >> 5;
    int P0 = blockIdx.x * 128;

    if (tid < NC) sb2[tid] = g_b2[tid];

    u64 acc2[4][4];
#pragma unroll
    for (int i = 0; i < 4; i++)
#pragma unroll
        for (int p = 0; p < 4; p++) acc2[i][p] = 0ull;
    float a2acc[4] = {0.f, 0.f, 0.f, 0.f};

    const float4* X4 = (const float4*)X;
    const float4* W4 = (const float4*)g_centers;

    for (int kc4 = 0; kc4 < DIM / 4; kc4 += KC / 4) {
#pragma unroll
        for (int r = 0; r < 4; r++) {
            int q = tid + r * 256;
            int p = q >> 3;
            int j = q & 7;
            float4 v = X4[(size_t)(P0 + p) * (DIM / 4) + kc4 + j];
            int kk = j * 4;
            Xs[(kk + 0) * XS_STRIDE + p] = v.x;
            Xs[(kk + 1) * XS_STRIDE + p] = v.y;
            Xs[(kk + 2) * XS_STRIDE + p] = v.z;
            Xs[(kk + 3) * XS_STRIDE + p] = v.w;
        }
#pragma unroll
        for (int r = 0; r < 2; r++) {
            int q = tid + r * 256;
            int c = q >> 3;
            int j = q & 7;
            float4 v = W4[(size_t)c * (DIM / 4) + kc4 + j];
            int kk = j * 4;
            Ws[(kk + 0) * WS_STRIDE + c] = v.x;
            Ws[(kk + 1) * WS_STRIDE + c] = v.y;
            Ws[(kk + 2) * WS_STRIDE + c] = v.z;
            Ws[(kk + 3) * WS_STRIDE + c] = v.w;
        }
        __syncthreads();
#pragma unroll 8
        for (int k = 0; k < KC; k++) {
            float4 xv = *(const float4*)&Xs[k * XS_STRIDE + tx * 4];
            ulonglong2 wA = *(const ulonglong2*)&Ws[k * WS_STRIDE + ty * 8];
            ulonglong2 wB = *(const ulonglong2*)&Ws[k * WS_STRIDE + ty * 8 + 4];
            if (ty == 0) {
                a2acc[0] += xv.x * xv.x;
                a2acc[1] += xv.y * xv.y;
                a2acc[2] += xv.z * xv.z;
                a2acc[3] += xv.w * xv.w;
            }
            u64 xd0 = pack2(xv.x), xd1 = pack2(xv.y);
            u64 xd2 = pack2(xv.z), xd3 = pack2(xv.w);
            fma2(acc2[0][0], xd0, wA.x); fma2(acc2[0][1], xd0, wA.y);
            fma2(acc2[0][2], xd0, wB.x); fma2(acc2[0][3], xd0, wB.y);
            fma2(acc2[1][0], xd1, wA.x); fma2(acc2[1][1], xd1, wA.y);
            fma2(acc2[1][2], xd1, wB.x); fma2(acc2[1][3], xd1, wB.y);
            fma2(acc2[2][0], xd2, wA.x); fma2(acc2[2][1], xd2, wA.y);
            fma2(acc2[2][2], xd2, wB.x); fma2(acc2[2][3], xd2, wB.y);
            fma2(acc2[3][0], xd3, wA.x); fma2(acc2[3][1], xd3, wA.y);
            fma2(acc2[3][2], xd3, wB.x); fma2(acc2[3][3], xd3, wB.y);
        }
        __syncthreads();
    }

    if (ty == 0) {
#pragma unroll
        for (int i = 0; i < 4; i++) sa2[tx * 4 + i] = a2acc[i];
    }
    __syncthreads();

#pragma unroll
    for (int i = 0; i < 4; i++) {
        float a2 = sa2[tx * 4 + i];
        float res[8];
#pragma unroll
        for (int p = 0; p < 4; p++) {
            float lo, hi;
            unpack2(acc2[i][p], lo, hi);
            float d0 = fmaxf(a2 + sb2[ty * 8 + 2 * p] - 2.0f * lo, 0.0f);
            float d1 = fmaxf(a2 + sb2[ty * 8 + 2 * p + 1] - 2.0f * hi, 0.0f);
            res[2 * p] = 1.0f / (sqrtf(d0) + 1e-8f);
            res[2 * p + 1] = 1.0f / (sqrtf(d1) + 1e-8f);
        }
        float* op = out + (size_t)(P0 + tx * 4 + i) * NC + ty * 8;
        *(float4*)&op[0] = *(float4*)&res[0];
        *(float4*)&op[4] = *(float4*)&res[4];
    }
}

// ============================================================================
extern "C" void kernel_launch(void* const* d_in, const int* in_sizes, int n_in,
                              void* d_out, int out_size) {
    const float* X = (const float*)d_in[0];
    float* out = (float*)d_out;

    const int smem_acc = (NC * DIM + NC + CHUNK) * 4;   // ~132.3 KB
    cudaFuncSetAttribute(accum_kernel,
                         cudaFuncAttributeMaxDynamicSharedMemorySize, smem_acc);

    init_kernel<<<NC, 128>>>(X);
    for (int it = 0; it < KM_ITERS; it++) {
        assign_kernel<<<N_PTS / 128, 256>>>(X);
        accum_kernel<<<ACC_BLOCKS, 256, smem_acc>>>(X);
        update_kernel<<<NC, 512>>>();
    }
    final_kernel<<<N_PTS / 128, 256>>>(X, out);
}

// round 13
// speedup vs baseline: 1.0980x; 1.0577x over previous
#include <cuda_runtime.h>
#include <math.h>
#include <stdint.h>

#define N_PTS 32768
#define DIM   512
#define NC    64
#define KM_ITERS 10

#define ACC_BLOCKS 128
#define CHUNK (N_PTS / ACC_BLOCKS)   // 256

#define KC 32
#define XS_STRIDE 132   // 128 + 4 pad, multiple of 4 (float4-aligned rows)
#define WS_STRIDE 72    // 64 + 8 pad, multiple of 4

// ---- scratch (no allocations allowed) ----
__device__ float g_centers[NC * DIM];
__device__ float g_b2[NC];
__device__ int   g_assign[N_PTS];
__device__ float g_psum[(size_t)ACC_BLOCKS * NC * DIM];   // 16 MB partials
__device__ float g_pcnt[ACC_BLOCKS * NC];

// ============================================================================
// init: centers = data[:64], b2 = ||c||^2.   grid 64, block 128
// ============================================================================
__global__ void init_kernel(const float* __restrict__ X) {
    int c = blockIdx.x;
    int t = threadIdx.x;           // 0..127, handles 4 dims via float4
    const float4* xr = (const float4*)(X + (size_t)c * DIM);
    float4 v = xr[t];
    ((float4*)(g_centers + (size_t)c * DIM))[t] = v;
    float s = v.x * v.x + v.y * v.y + v.z * v.z + v.w * v.w;
    __shared__ float red[128];
    red[t] = s;
    __syncthreads();
    for (int o = 64; o > 0; o >>= 1) {
        if (t < o) red[t] += red[t + o];
        __syncthreads();
    }
    if (t == 0) g_b2[c] = red[0];
}

// ============================================================================
// assign: argmin_c ( b2[c] - 2 * x . c )   (dropping constant ||x||^2)
// block tile: 128 points x 64 clusters, 256 threads, thread tile 4x8
// grid = N_PTS/128 = 256.  (proven round-1 scalar FFMA mainloop)
// ============================================================================
__global__ __launch_bounds__(256) void assign_kernel(const float* __restrict__ X) {
    __shared__ __align__(16) float Xs[KC * XS_STRIDE];
    __shared__ __align__(16) float Ws[KC * WS_STRIDE];
    __shared__ float sb2[NC];
    __shared__ float sval[128 * 8];
    __shared__ int   sidx[128 * 8];

    int tid = threadIdx.x;
    int tx = tid & 31;        // point group: points 4*tx .. 4*tx+3
    int ty = tid >> 5;        // cluster group: clusters 8*ty .. 8*ty+7
    int P0 = blockIdx.x * 128;

    if (tid < NC) sb2[tid] = g_b2[tid];

    float acc[4][8];
#pragma unroll
    for (int i = 0; i < 4; i++)
#pragma unroll
        for (int j = 0; j < 8; j++) acc[i][j] = 0.0f;

    const float4* X4 = (const float4*)X;
    const float4* W4 = (const float4*)g_centers;

    for (int kc4 = 0; kc4 < DIM / 4; kc4 += KC / 4) {
        // load 128x32 X tile, transposed into Xs[k][p]
#pragma unroll
        for (int r = 0; r < 4; r++) {
            int q = tid + r * 256;           // 0..1023
            int p = q >> 3;                  // 0..127
            int j = q & 7;                   // float4 within the 32-k chunk
            float4 v = X4[(size_t)(P0 + p) * (DIM / 4) + kc4 + j];
            int kk = j * 4;
            Xs[(kk + 0) * XS_STRIDE + p] = v.x;
            Xs[(kk + 1) * XS_STRIDE + p] = v.y;
            Xs[(kk + 2) * XS_STRIDE + p] = v.z;
            Xs[(kk + 3) * XS_STRIDE + p] = v.w;
        }
        // load 64x32 W tile, transposed into Ws[k][c]
#pragma unroll
        for (int r = 0; r < 2; r++) {
            int q = tid + r * 256;           // 0..511
            int c = q >> 3;                  // 0..63
            int j = q & 7;
            float4 v = W4[(size_t)c * (DIM / 4) + kc4 + j];
            int kk = j * 4;
            Ws[(kk + 0) * WS_STRIDE + c] = v.x;
            Ws[(kk + 1) * WS_STRIDE + c] = v.y;
            Ws[(kk + 2) * WS_STRIDE + c] = v.z;
            Ws[(kk + 3) * WS_STRIDE + c] = v.w;
        }
        __syncthreads();
#pragma unroll 8
        for (int k = 0; k < KC; k++) {
            float xr[4], wr[8];
            *(float4*)&xr[0] = *(const float4*)&Xs[k * XS_STRIDE + tx * 4];
            *(float4*)&wr[0] = *(const float4*)&Ws[k * WS_STRIDE + ty * 8];
            *(float4*)&wr[4] = *(const float4*)&Ws[k * WS_STRIDE + ty * 8 + 4];
#pragma unroll
            for (int i = 0; i < 4; i++)
#pragma unroll
                for (int j = 0; j < 8; j++)
                    acc[i][j] += xr[i] * wr[j];
        }
        __syncthreads();
    }

    // per-thread argmin over its 8 clusters (ascending index, strict <)
#pragma unroll
    for (int i = 0; i < 4; i++) {
        float mv = 3.4e38f;
        int mi = 0;
#pragma unroll
        for (int j = 0; j < 8; j++) {
            float s = sb2[ty * 8 + j] - 2.0f * acc[i][j];
            if (s < mv) { mv = s; mi = ty * 8 + j; }
        }
        int p = tx * 4 + i;
        sval[p * 8 + ty] = mv;
        sidx[p * 8 + ty] = mi;
    }
    __syncthreads();
    // reduce 8 candidates per point (ascending ty == ascending cluster ranges)
    if (tid < 128) {
        float mv = sval[tid * 8];
        int mi = sidx[tid * 8];
#pragma unroll
        for (int t = 1; t < 8; t++) {
            float v = sval[tid * 8 + t];
            if (v < mv) { mv = v; mi = sidx[tid * 8 + t]; }
        }
        g_assign[P0 + tid] = mi;
    }
}

// ============================================================================
// accumulate: per-block shared accumulator (64x512 fp32 = 128 KB), warp-private
// dim slices, 4-point batching for load MLP + pipelined RMW chains.
// grid ACC_BLOCKS, block 256.
// ============================================================================
__global__ __launch_bounds__(256) void accum_kernel(const float* __restrict__ X) {
    extern __shared__ float sm[];
    float* sacc = sm;                       // NC*DIM
    float* scnt = sm + NC * DIM;            // NC
    int*   sassign = (int*)(scnt + NC);     // CHUNK

    int tid = threadIdx.x;
    for (int i = tid; i < NC * DIM; i += 256) sacc[i] = 0.0f;
    for (int i = tid; i < NC; i += 256) scnt[i] = 0.0f;
    int base = blockIdx.x * CHUNK;
    for (int i = tid; i < CHUNK; i += 256) sassign[i] = g_assign[base + i];
    __syncthreads();

    int w = tid >> 5, lane = tid & 31;
    int doff = w * 32 + lane;               // float2 offset: warp w owns dims [64w,64w+64)
    const float2* X2 = (const float2*)X;
    float2* sacc2 = (float2*)sacc;

    for (int p = 0; p < CHUNK; p += 4) {
        int a0 = sassign[p], a1 = sassign[p + 1];
        int a2 = sassign[p + 2], a3 = sassign[p + 3];
        float2 v0 = X2[(size_t)(base + p + 0) * (DIM / 2) + doff];
        float2 v1 = X2[(size_t)(base + p + 1) * (DIM / 2) + doff];
        float2 v2 = X2[(size_t)(base + p + 2) * (DIM / 2) + doff];
        float2 v3 = X2[(size_t)(base + p + 3) * (DIM / 2) + doff];
        float2* q0 = &sacc2[a0 * (DIM / 2) + doff];
        float2 c0 = *q0; c0.x += v0.x; c0.y += v0.y; *q0 = c0;
        float2* q1 = &sacc2[a1 * (DIM / 2) + doff];
        float2 c1 = *q1; c1.x += v1.x; c1.y += v1.y; *q1 = c1;
        float2* q2 = &sacc2[a2 * (DIM / 2) + doff];
        float2 c2 = *q2; c2.x += v2.x; c2.y += v2.y; *q2 = c2;
        float2* q3 = &sacc2[a3 * (DIM / 2) + doff];
        float2 c3 = *q3; c3.x += v3.x; c3.y += v3.y; *q3 = c3;
    }
    __syncthreads();
    for (int i = tid; i < CHUNK; i += 256) atomicAdd(&scnt[sassign[i]], 1.0f);
    __syncthreads();

    float* ps = g_psum + (size_t)blockIdx.x * NC * DIM;
    for (int i = tid; i < NC * DIM; i += 256) ps[i] = sacc[i];
    if (tid < NC) g_pcnt[blockIdx.x * NC + tid] = scnt[tid];
}

// ============================================================================
// update1: reduce partials -> new centers (keep old if empty).
// grid 256 (cluster c = bid>>2, dim chunk = bid&3), block 128 (one dim each)
// ============================================================================
__global__ __launch_bounds__(128) void update1_kernel() {
    int c = blockIdx.x >> 2;
    int ch = blockIdx.x & 3;
    int t = threadIdx.x;
    int d = ch * 128 + t;
    __shared__ float red[128];

    // count for this cluster (redundant across the 4 chunk-blocks; cheap)
    red[t] = g_pcnt[t * NC + c];             // ACC_BLOCKS == 128
    __syncthreads();
    for (int o = 64; o > 0; o >>= 1) {
        if (t < o) red[t] += red[t + o];
        __syncthreads();
    }
    float cnt = red[0];

    const float* ps = g_psum + (size_t)c * DIM + d;
    float s0 = 0.f, s1 = 0.f, s2 = 0.f, s3 = 0.f;
#pragma unroll 8
    for (int b = 0; b < ACC_BLOCKS; b += 4) {
        s0 += ps[(size_t)(b + 0) * (NC * DIM)];
        s1 += ps[(size_t)(b + 1) * (NC * DIM)];
        s2 += ps[(size_t)(b + 2) * (NC * DIM)];
        s3 += ps[(size_t)(b + 3) * (NC * DIM)];
    }
    float s = (s0 + s1) + (s2 + s3);

    float oldc = g_centers[c * DIM + d];
    g_centers[c * DIM + d] = (cnt > 0.0f) ? s / cnt : oldc;
}

// ============================================================================
// update2: b2[c] = ||center_c||^2.   grid 64, block 128 (float4 each)
// ============================================================================
__global__ __launch_bounds__(128) void update2_kernel() {
    int c = blockIdx.x;
    int t = threadIdx.x;
    float4 v = ((const float4*)(g_centers + (size_t)c * DIM))[t];
    float s = v.x * v.x + v.y * v.y + v.z * v.z + v.w * v.w;
    __shared__ float red[128];
    red[t] = s;
    __syncthreads();
    for (int o = 64; o > 0; o >>= 1) {
        if (t < o) red[t] += red[t + o];
        __syncthreads();
    }
    if (t == 0) g_b2[c] = red[0];
}

// ============================================================================
// final: out[p][c] = 1 / (sqrt(max(||x||^2 + ||c||^2 - 2 x.c, 0)) + 1e-8)
// same GEMM structure; ||x||^2 fused into warp ty==0 of the mainloop
// ============================================================================
__global__ __launch_bounds__(256) void final_kernel(const float* __restrict__ X,
                                                    float* __restrict__ out) {
    __shared__ __align__(16) float Xs[KC * XS_STRIDE];
    __shared__ __align__(16) float Ws[KC * WS_STRIDE];
    __shared__ float sb2[NC];
    __shared__ float sa2[128];

    int tid = threadIdx.x;
    int tx = tid & 31, ty = tid >> 5;
    int P0 = blockIdx.x * 128;

    if (tid < NC) sb2[tid] = g_b2[tid];

    float acc[4][8];
#pragma unroll
    for (int i = 0; i < 4; i++)
#pragma unroll
        for (int j = 0; j < 8; j++) acc[i][j] = 0.0f;
    float a2acc[4] = {0.f, 0.f, 0.f, 0.f};

    const float4* X4 = (const float4*)X;
    const float4* W4 = (const float4*)g_centers;

    for (int kc4 = 0; kc4 < DIM / 4; kc4 += KC / 4) {
#pragma unroll
        for (int r = 0; r < 4; r++) {
            int q = tid + r * 256;
            int p = q >> 3;
            int j = q & 7;
            float4 v = X4[(size_t)(P0 + p) * (DIM / 4) + kc4 + j];
            int kk = j * 4;
            Xs[(kk + 0) * XS_STRIDE + p] = v.x;
            Xs[(kk + 1) * XS_STRIDE + p] = v.y;
            Xs[(kk + 2) * XS_STRIDE + p] = v.z;
            Xs[(kk + 3) * XS_STRIDE + p] = v.w;
        }
#pragma unroll
        for (int r = 0; r < 2; r++) {
            int q = tid + r * 256;
            int c = q >> 3;
            int j = q & 7;
            float4 v = W4[(size_t)c * (DIM / 4) + kc4 + j];
            int kk = j * 4;
            Ws[(kk + 0) * WS_STRIDE + c] = v.x;
            Ws[(kk + 1) * WS_STRIDE + c] = v.y;
            Ws[(kk + 2) * WS_STRIDE + c] = v.z;
            Ws[(kk + 3) * WS_STRIDE + c] = v.w;
        }
        __syncthreads();
#pragma unroll 8
        for (int k = 0; k < KC; k++) {
            float xr[4], wr[8];
            *(float4*)&xr[0] = *(const float4*)&Xs[k * XS_STRIDE + tx * 4];
            *(float4*)&wr[0] = *(const float4*)&Ws[k * WS_STRIDE + ty * 8];
            *(float4*)&wr[4] = *(const float4*)&Ws[k * WS_STRIDE + ty * 8 + 4];
            if (ty == 0) {
#pragma unroll
                for (int i = 0; i < 4; i++) a2acc[i] += xr[i] * xr[i];
            }
#pragma unroll
            for (int i = 0; i < 4; i++)
#pragma unroll
                for (int j = 0; j < 8; j++)
                    acc[i][j] += xr[i] * wr[j];
        }
        __syncthreads();
    }

    if (ty == 0) {
#pragma unroll
        for (int i = 0; i < 4; i++) sa2[tx * 4 + i] = a2acc[i];
    }
    __syncthreads();

#pragma unroll
    for (int i = 0; i < 4; i++) {
        float a2 = sa2[tx * 4 + i];
        float res[8];
#pragma unroll
        for (int j = 0; j < 8; j++) {
            float d2 = a2 + sb2[ty * 8 + j] - 2.0f * acc[i][j];
            d2 = fmaxf(d2, 0.0f);
            res[j] = 1.0f / (sqrtf(d2) + 1e-8f);
        }
        float* op = out + (size_t)(P0 + tx * 4 + i) * NC + ty * 8;
        *(float4*)&op[0] = *(float4*)&res[0];
        *(float4*)&op[4] = *(float4*)&res[4];
    }
}

// ============================================================================
extern "C" void kernel_launch(void* const* d_in, const int* in_sizes, int n_in,
                              void* d_out, int out_size) {
    const float* X = (const float*)d_in[0];
    float* out = (float*)d_out;

    const int smem_acc = (NC * DIM + NC + CHUNK) * 4;   // ~132.3 KB
    cudaFuncSetAttribute(accum_kernel,
                         cudaFuncAttributeMaxDynamicSharedMemorySize, smem_acc);

    init_kernel<<<NC, 128>>>(X);
    for (int it = 0; it < KM_ITERS; it++) {
        assign_kernel<<<N_PTS / 128, 256>>>(X);
        accum_kernel<<<ACC_BLOCKS, 256, smem_acc>>>(X);
        update1_kernel<<<NC * 4, 128>>>();
        update2_kernel<<<NC, 128>>>();
    }
    final_kernel<<<N_PTS / 128, 256>>>(X, out);
}